// round 2
// baseline (speedup 1.0000x reference)
#include <cuda_runtime.h>
#include <cuda_bf16.h>
#include <math.h>

// Problem constants
#define BB   64
#define SS   512
#define DD   1024
#define HH   512
#define TT   25
#define MROWS (BB*SS)          // 32768

// -------- scratch (allocation-free: __device__ globals) --------
__device__ float g_H[MROWS * HH];          // 64 MB hidden activations
__device__ float g_E[MROWS * TT + 32];     // emissions (+pad)
__device__ float g_ll[BB];                 // per-batch log-likelihood

// ============================================================================
// GEMM1: H = gelu(X @ W1 + b1)    X[32768,1024]  W1[1024,512]
// classic 128x128x8 SMEM-tiled fp32, 256 threads, 8x8 per thread
// ============================================================================
#define BM 128
#define BN 128
#define BK 8

__global__ __launch_bounds__(256, 2)
void gemm1_gelu_kernel(const float* __restrict__ X,
                       const float* __restrict__ W1,
                       const float* __restrict__ b1)
{
    __shared__ float As[BK][BM];
    __shared__ float Bs[BK][BN];

    const int tid = threadIdx.x;
    const int m0 = blockIdx.y * BM;
    const int n0 = blockIdx.x * BN;
    const int tx = tid & 15;        // 0..15
    const int ty = tid >> 4;        // 0..15

    const int arow = tid >> 1;
    const int acol = (tid & 1) * 4;
    const int brow = tid >> 5;
    const int bcol = (tid & 31) * 4;

    const float* Aptr = X + (size_t)(m0 + arow) * DD + acol;
    const float* Bptr = W1 + (size_t)brow * HH + n0 + bcol;

    float c[8][8];
    #pragma unroll
    for (int i = 0; i < 8; i++)
        #pragma unroll
        for (int j = 0; j < 8; j++) c[i][j] = 0.f;

    for (int k0 = 0; k0 < DD; k0 += BK) {
        float4 av = *(const float4*)(Aptr + k0);
        float4 bv = *(const float4*)(Bptr + (size_t)k0 * HH);

        As[acol + 0][arow] = av.x;
        As[acol + 1][arow] = av.y;
        As[acol + 2][arow] = av.z;
        As[acol + 3][arow] = av.w;
        *(float4*)&Bs[brow][bcol] = bv;
        __syncthreads();

        #pragma unroll
        for (int kk = 0; kk < BK; kk++) {
            float a[8], bfr[8];
            *(float4*)(a)       = *(const float4*)&As[kk][ty * 8];
            *(float4*)(a + 4)   = *(const float4*)&As[kk][ty * 8 + 4];
            *(float4*)(bfr)     = *(const float4*)&Bs[kk][tx * 8];
            *(float4*)(bfr + 4) = *(const float4*)&Bs[kk][tx * 8 + 4];
            #pragma unroll
            for (int i = 0; i < 8; i++)
                #pragma unroll
                for (int j = 0; j < 8; j++)
                    c[i][j] += a[i] * bfr[j];
        }
        __syncthreads();
    }

    // epilogue: bias + exact gelu, store
    #pragma unroll
    for (int i = 0; i < 8; i++) {
        const int row = m0 + ty * 8 + i;
        float* out = g_H + (size_t)row * HH + n0 + tx * 8;
        #pragma unroll
        for (int j = 0; j < 8; j++) {
            float v = c[i][j] + b1[n0 + tx * 8 + j];
            v = 0.5f * v * (1.0f + erff(v * 0.70710678118654752f));
            out[j] = v;
        }
    }
}

// ============================================================================
// GEMM2: E = H @ W2 + b2    H[32768,512]  W2[512,25]
// warp per row; W2 read from global (51KB, L1-resident); h broadcast via shfl
// ============================================================================
__global__ __launch_bounds__(256)
void gemm2_kernel(const float* __restrict__ W2,
                  const float* __restrict__ b2)
{
    const int tid = threadIdx.x;
    const int lane = tid & 31;
    const int warp = tid >> 5;
    const int warpsPerBlock = blockDim.x >> 5;
    const int gwarp = blockIdx.x * warpsPerBlock + warp;
    const int nWarps = gridDim.x * warpsPerBlock;

    const int colIdx = (lane < TT) ? lane : (TT - 1);
    const float bias = b2[colIdx];

    for (int row = gwarp; row < MROWS; row += nWarps) {
        float h[16];
        const float4* hp = (const float4*)(g_H + (size_t)row * HH);
        #pragma unroll
        for (int i = 0; i < 4; i++) {
            float4 v = hp[lane + 32 * i];
            h[i * 4 + 0] = v.x; h[i * 4 + 1] = v.y;
            h[i * 4 + 2] = v.z; h[i * 4 + 3] = v.w;
        }
        float acc = 0.f;
        #pragma unroll
        for (int k = 0; k < HH; k++) {
            float hk = __shfl_sync(0xffffffffu, h[((k >> 7) << 2) + (k & 3)], (k >> 2) & 31);
            acc += hk * __ldg(&W2[k * TT + colIdx]);
        }
        if (lane < TT) g_E[(size_t)row * TT + lane] = acc + bias;
    }
}

// ============================================================================
// CRF: one warp per batch element. numerator + forward scan (log semiring)
// Handles mask delivered as float32 / int32 / packed bytes, labels int64/int32.
// ============================================================================
__global__ void crf_kernel(const float* __restrict__ start_t,
                           const float* __restrict__ end_t,
                           const float* __restrict__ trans,
                           const void*  __restrict__ labels_raw,
                           const void*  __restrict__ mask_raw)
{
    __shared__ float trans_sh[TT * TT];
    __shared__ float alpha_sh[32];
    __shared__ unsigned char msh[SS];

    const int b = blockIdx.x;
    const int lane = threadIdx.x;
    const unsigned full = 0xffffffffu;

    for (int i = lane; i < TT * TT; i += 32) trans_sh[i] = trans[i];

    // ---- detect label dtype: int64 vs int32 (high words of first 32 entries) ----
    const int* li = (const int*)labels_raw;
    unsigned ball = __ballot_sync(full, li[2 * lane + 1] == 0);
    const int lstride = (ball == full) ? 2 : 1;

    // ---- detect mask encoding by inspecting first 256 words ----
    const unsigned* mw = (const unsigned*)mask_raw;
    unsigned any_high = 0, any_float = 0;
    for (int i = lane; i < 256; i += 32) {
        unsigned w = mw[i];
        any_float |= (w == 0x3F800000u);
        any_high  |= (w & 0xFFFFFF00u) && (w != 0x3F800000u);
    }
    const bool is_float = __ballot_sync(full, any_float != 0) != 0;
    const bool is_byte  = !is_float && (__ballot_sync(full, any_high != 0) != 0);

    const int base = b * SS;

    // decode mask for this batch into shared bytes
    for (int t = lane; t < SS; t += 32) {
        unsigned char mv;
        if (is_float)      mv = (((const float*)mask_raw)[base + t] != 0.f);
        else if (is_byte)  mv = (((const unsigned char*)mask_raw)[base + t] != 0);
        else               mv = (((const int*)mask_raw)[base + t] != 0);
        msh[t] = mv;
    }
    __syncwarp();

    const float* Eb = g_E + (size_t)base * TT;

    // ---- numerator ----
    float acc = 0.f;
    int cnt = 0;
    for (int t = lane; t < SS; t += 32) cnt += msh[t] ? 1 : 0;
    for (int t = 1 + lane; t < SS; t += 32) {
        if (msh[t]) {
            int lt = li[(base + t) * lstride];
            int lp = li[(base + t - 1) * lstride];
            acc += trans_sh[lp * TT + lt] + Eb[t * TT + lt];
        }
    }
    #pragma unroll
    for (int off = 16; off > 0; off >>= 1) {
        acc += __shfl_xor_sync(full, acc, off);
        cnt += __shfl_xor_sync(full, cnt, off);
    }

    // ---- forward scan ----
    float alpha = (lane < TT) ? (start_t[lane] + Eb[lane]) : -INFINITY;

    float e_next = (lane < TT) ? Eb[1 * TT + lane] : 0.f;
    unsigned char m_next = msh[1];

    for (int t = 1; t < SS; t++) {
        float e_cur = e_next;
        unsigned char m_cur = m_next;
        if (t + 1 < SS) {
            e_next = (lane < TT) ? Eb[(t + 1) * TT + lane] : 0.f;
            m_next = msh[t + 1];
        }
        alpha_sh[lane] = alpha;
        __syncwarp();
        // shift by lane-0 alpha (bounded spread => safe logsumexp shift)
        float M = __shfl_sync(full, alpha, 0);
        float s = 0.f;
        if (lane < TT) {
            #pragma unroll
            for (int i = 0; i < TT; i++)
                s += __expf(alpha_sh[i] - M + trans_sh[i * TT + lane]);
        }
        float nv = e_cur + M + __logf(s);
        if (lane < TT && m_cur) alpha = nv;
        __syncwarp();
    }

    // log_Z = logsumexp(alpha + end_t)
    float v = (lane < TT) ? (alpha + end_t[lane]) : -INFINITY;
    float M2 = v;
    #pragma unroll
    for (int off = 16; off > 0; off >>= 1)
        M2 = fmaxf(M2, __shfl_xor_sync(full, M2, off));
    float s2 = (lane < TT) ? __expf(v - M2) : 0.f;
    #pragma unroll
    for (int off = 16; off > 0; off >>= 1)
        s2 += __shfl_xor_sync(full, s2, off);

    if (lane == 0) {
        int lab0 = li[base * lstride];
        float score0 = start_t[lab0] + Eb[lab0];
        int last_idx = cnt - 1;
        int last_tag = li[(base + last_idx) * lstride];
        float numerator = score0 + acc + end_t[last_tag];
        float logZ = M2 + __logf(s2);
        g_ll[b] = numerator - logZ;
    }
}

// ============================================================================
// finalize: out = -mean(ll)
// ============================================================================
__global__ void finalize_kernel(float* __restrict__ out)
{
    __shared__ float sbuf[2];
    const int l = threadIdx.x; // 64 threads
    float v = g_ll[l];
    #pragma unroll
    for (int off = 16; off > 0; off >>= 1)
        v += __shfl_xor_sync(0xffffffffu, v, off);
    if ((l & 31) == 0) sbuf[l >> 5] = v;
    __syncthreads();
    if (l == 0) out[0] = -(sbuf[0] + sbuf[1]) / (float)BB;
}

// ============================================================================
// launch
// ============================================================================
extern "C" void kernel_launch(void* const* d_in, const int* in_sizes, int n_in,
                              void* d_out, int out_size)
{
    const float* X       = (const float*)d_in[0];
    const float* W1      = (const float*)d_in[1];
    const float* b1      = (const float*)d_in[2];
    const float* W2      = (const float*)d_in[3];
    const float* b2      = (const float*)d_in[4];
    const float* start_t = (const float*)d_in[5];
    const float* end_t   = (const float*)d_in[6];
    const float* trans   = (const float*)d_in[7];
    const void*  labels  = d_in[8];
    const void*  mask    = d_in[9];
    float* out = (float*)d_out;

    dim3 g1(HH / BN, MROWS / BM);
    gemm1_gelu_kernel<<<g1, 256>>>(X, W1, b1);

    gemm2_kernel<<<1024, 256>>>(W2, b2);

    crf_kernel<<<BB, 32>>>(start_t, end_t, trans, labels, mask);

    finalize_kernel<<<1, 64>>>(out);
}

// round 3
// speedup vs baseline: 1.7990x; 1.7990x over previous
#include <cuda_runtime.h>
#include <cuda_bf16.h>
#include <math.h>
#include <stdint.h>

// Problem constants
#define BB   64
#define SS   512
#define DD   1024
#define HH   512
#define TT   25
#define MROWS (BB*SS)          // 32768

// -------- scratch (allocation-free: __device__ globals) --------
__device__ uint4 g_Xs[(size_t)MROWS * DD / 8];   // 64 MB bf16 X, tiled+swizzled
__device__ uint4 g_W1s[(size_t)DD * HH / 8];     // 1 MB bf16 W1, tiled+swizzled
__device__ float g_H[(size_t)MROWS * HH];        // 64 MB hidden activations
__device__ float g_E[(size_t)MROWS * TT + 32];   // emissions (+pad)
__device__ float g_ll[BB];                       // per-batch log-likelihood

// ============================================================================
// Convert X -> bf16 tiles [mtile 256][ktile 32][row 128][chunk 4 x 16B],
// chunk swizzled: c' = c ^ (r&3) ^ ((r>>2)&1)
// ============================================================================
__global__ __launch_bounds__(256)
void convert_X_kernel(const float* __restrict__ X)
{
    int id = blockIdx.x * 256 + threadIdx.x;      // one 16B output chunk
    int tile   = id >> 9;                          // 512 chunks per tile
    int within = id & 511;
    int r  = within >> 2;
    int cp = within & 3;
    int mtile = tile >> 5;
    int ktile = tile & 31;
    int sw = (r & 3) ^ ((r >> 2) & 1);
    int c  = cp ^ sw;
    int m = mtile * 128 + r;
    int k = ktile * 32 + c * 8;
    const float4* src = (const float4*)(X + (size_t)m * DD + k);
    float4 x0 = src[0], x1 = src[1];
    __nv_bfloat162 p0 = __floats2bfloat162_rn(x0.x, x0.y);
    __nv_bfloat162 p1 = __floats2bfloat162_rn(x0.z, x0.w);
    __nv_bfloat162 p2 = __floats2bfloat162_rn(x1.x, x1.y);
    __nv_bfloat162 p3 = __floats2bfloat162_rn(x1.z, x1.w);
    uint4 out;
    out.x = *(uint32_t*)&p0; out.y = *(uint32_t*)&p1;
    out.z = *(uint32_t*)&p2; out.w = *(uint32_t*)&p3;
    g_Xs[id] = out;
}

// ============================================================================
// Convert W1 -> bf16 tiles [ktile 32][ntile 4][krow 32][chunk 16 x 16B],
// chunk swizzled: c' = c ^ (k&7)
// ============================================================================
__global__ __launch_bounds__(256)
void convert_W1_kernel(const float* __restrict__ W1)
{
    int id = blockIdx.x * 256 + threadIdx.x;      // one 16B output chunk
    int tile   = id >> 9;
    int within = id & 511;
    int k  = within >> 4;
    int cp = within & 15;
    int ktile = tile >> 2;
    int ntile = tile & 3;
    int c = cp ^ (k & 7);
    int krow = ktile * 32 + k;
    int n = ntile * 128 + c * 8;
    const float4* src = (const float4*)(W1 + (size_t)krow * HH + n);
    float4 x0 = src[0], x1 = src[1];
    __nv_bfloat162 p0 = __floats2bfloat162_rn(x0.x, x0.y);
    __nv_bfloat162 p1 = __floats2bfloat162_rn(x0.z, x0.w);
    __nv_bfloat162 p2 = __floats2bfloat162_rn(x1.x, x1.y);
    __nv_bfloat162 p3 = __floats2bfloat162_rn(x1.z, x1.w);
    uint4 out;
    out.x = *(uint32_t*)&p0; out.y = *(uint32_t*)&p1;
    out.z = *(uint32_t*)&p2; out.w = *(uint32_t*)&p3;
    g_W1s[id] = out;
}

// ============================================================================
// GEMM1 (tensor cores): H = gelu(X @ W1 + b1)
// 128x128x32 tiles, 3-stage cp.async pipeline, mma.sync m16n8k16 bf16
// ============================================================================
#define STAGES 3
#define NIT (DD / 32)   // 32 k-iterations

__device__ __forceinline__ void cp_async16(uint32_t saddr, const void* gaddr) {
    asm volatile("cp.async.cg.shared.global [%0], [%1], 16;\n"
                 :: "r"(saddr), "l"(gaddr));
}
__device__ __forceinline__ void cp_commit() {
    asm volatile("cp.async.commit_group;\n");
}
__device__ __forceinline__ void cp_wait2() {
    asm volatile("cp.async.wait_group 2;\n");
}
__device__ __forceinline__ void ldmatrix_x4(uint32_t* r, uint32_t addr) {
    asm volatile("ldmatrix.sync.aligned.m8n8.x4.shared.b16 {%0,%1,%2,%3}, [%4];"
                 : "=r"(r[0]), "=r"(r[1]), "=r"(r[2]), "=r"(r[3]) : "r"(addr));
}
__device__ __forceinline__ void ldmatrix_x4_trans(uint32_t* r, uint32_t addr) {
    asm volatile("ldmatrix.sync.aligned.m8n8.x4.trans.shared.b16 {%0,%1,%2,%3}, [%4];"
                 : "=r"(r[0]), "=r"(r[1]), "=r"(r[2]), "=r"(r[3]) : "r"(addr));
}
__device__ __forceinline__ void mma_bf16(float* c, const uint32_t* a,
                                         uint32_t b0, uint32_t b1) {
    asm volatile("mma.sync.aligned.m16n8k16.row.col.f32.bf16.bf16.f32 "
                 "{%0,%1,%2,%3},{%4,%5,%6,%7},{%8,%9},{%0,%1,%2,%3};"
                 : "+f"(c[0]), "+f"(c[1]), "+f"(c[2]), "+f"(c[3])
                 : "r"(a[0]), "r"(a[1]), "r"(a[2]), "r"(a[3]), "r"(b0), "r"(b1));
}

__global__ __launch_bounds__(256)
void gemm1_bf16_kernel(const float* __restrict__ b1)
{
    __shared__ __align__(16) unsigned char smA[STAGES][8192];  // 128x32 bf16
    __shared__ __align__(16) unsigned char smB[STAGES][8192];  // 32x128 bf16

    const int tid  = threadIdx.x;
    const int lane = tid & 31;
    const int w    = tid >> 5;
    const int wm   = w & 3;    // 0..3 (m)
    const int wn   = w >> 2;   // 0..1 (n)
    const int mtile = blockIdx.y;
    const int ntile = blockIdx.x;

    uint32_t sA0 = (uint32_t)__cvta_generic_to_shared(&smA[0][0]);
    uint32_t sB0 = (uint32_t)__cvta_generic_to_shared(&smB[0][0]);

    const int cid0 = tid;          // copy chunk ids (2 per buffer per thread)
    const int cid1 = tid + 256;

    auto issue = [&](int stage, int it) {
        const uint4* gA = g_Xs + ((size_t)(mtile * 32 + it)) * 512;
        const uint4* gB = g_W1s + ((size_t)(it * 4 + ntile)) * 512;
        uint32_t sa = sA0 + stage * 8192;
        uint32_t sb = sB0 + stage * 8192;
        cp_async16(sa + cid0 * 16, gA + cid0);
        cp_async16(sa + cid1 * 16, gA + cid1);
        cp_async16(sb + cid0 * 16, gB + cid0);
        cp_async16(sb + cid1 * 16, gB + cid1);
    };

    // --- precompute lane-dependent ldmatrix offsets ---
    // A: row rA = wm*32 + im*16 + (lane&15); chunk = (2s + (lane>>4)) ^ swzA
    int rA0 = wm * 32 + (lane & 15);
    int rA1 = rA0 + 16;
    int swzA0 = (rA0 & 3) ^ ((rA0 >> 2) & 1);
    int swzA1 = (rA1 & 3) ^ ((rA1 >> 2) & 1);
    int caBase = lane >> 4;  // 0 or 1
    // B: row k = 16s + (lane&15); chunk = (wn*8 + inb*2 + (lane>>4)) ^ (lane&7)
    int kBoff = lane & 15;
    int cbBase = wn * 8 + (lane >> 4);
    int kx = lane & 7;

    float c[2][8][4];
    #pragma unroll
    for (int im = 0; im < 2; im++)
        #pragma unroll
        for (int in = 0; in < 8; in++)
            #pragma unroll
            for (int r = 0; r < 4; r++) c[im][in][r] = 0.f;

    issue(0, 0); cp_commit();
    issue(1, 1); cp_commit();

    for (int it = 0; it < NIT; ++it) {
        if (it + 2 < NIT) issue((it + 2) % STAGES, it + 2);
        cp_commit();
        cp_wait2();
        __syncthreads();

        const int st = it % STAGES;
        uint32_t abase = sA0 + st * 8192;
        uint32_t bbase = sB0 + st * 8192;

        #pragma unroll
        for (int s = 0; s < 2; s++) {
            uint32_t a[2][4];
            {
                int ch0 = (2 * s + caBase) ^ swzA0;
                int ch1 = (2 * s + caBase) ^ swzA1;
                ldmatrix_x4(a[0], abase + rA0 * 64 + ch0 * 16);
                ldmatrix_x4(a[1], abase + rA1 * 64 + ch1 * 16);
            }
            uint32_t bt[4][4];
            #pragma unroll
            for (int inb = 0; inb < 4; inb++) {
                int ch = (cbBase + inb * 2) ^ kx;
                ldmatrix_x4_trans(bt[inb], bbase + (16 * s + kBoff) * 256 + ch * 16);
            }
            #pragma unroll
            for (int im = 0; im < 2; im++)
                #pragma unroll
                for (int in = 0; in < 8; in++) {
                    uint32_t b0 = bt[in >> 1][(in & 1) * 2];
                    uint32_t b1r = bt[in >> 1][(in & 1) * 2 + 1];
                    mma_bf16(c[im][in], a[im], b0, b1r);
                }
        }
        __syncthreads();
    }

    // --- epilogue: bias + exact gelu, write fp32 H ---
    const int g  = lane >> 2;
    const int tg = lane & 3;
    const int mbase = mtile * 128 + wm * 32;
    const int nbase = ntile * 128 + wn * 64;
    #pragma unroll
    for (int im = 0; im < 2; im++) {
        #pragma unroll
        for (int in = 0; in < 8; in++) {
            int col = nbase + in * 8 + tg * 2;
            float bias0 = __ldg(&b1[col]);
            float bias1 = __ldg(&b1[col + 1]);
            #pragma unroll
            for (int h = 0; h < 2; h++) {
                int row = mbase + im * 16 + g + 8 * h;
                float v0 = c[im][in][2 * h]     + bias0;
                float v1 = c[im][in][2 * h + 1] + bias1;
                v0 = 0.5f * v0 * (1.0f + erff(v0 * 0.70710678118654752f));
                v1 = 0.5f * v1 * (1.0f + erff(v1 * 0.70710678118654752f));
                float2 o = make_float2(v0, v1);
                *(float2*)(g_H + (size_t)row * HH + col) = o;
            }
        }
    }
}

// ============================================================================
// GEMM2: E = H @ W2 + b2    H[32768,512]  W2[512,25]
// warp per row; W2 read from global (L1/L2-resident); h broadcast via shfl
// ============================================================================
__global__ __launch_bounds__(256)
void gemm2_kernel(const float* __restrict__ W2,
                  const float* __restrict__ b2)
{
    const int tid = threadIdx.x;
    const int lane = tid & 31;
    const int warp = tid >> 5;
    const int warpsPerBlock = blockDim.x >> 5;
    const int gwarp = blockIdx.x * warpsPerBlock + warp;
    const int nWarps = gridDim.x * warpsPerBlock;

    const int colIdx = (lane < TT) ? lane : (TT - 1);
    const float bias = b2[colIdx];

    for (int row = gwarp; row < MROWS; row += nWarps) {
        float h[16];
        const float4* hp = (const float4*)(g_H + (size_t)row * HH);
        #pragma unroll
        for (int i = 0; i < 4; i++) {
            float4 v = hp[lane + 32 * i];
            h[i * 4 + 0] = v.x; h[i * 4 + 1] = v.y;
            h[i * 4 + 2] = v.z; h[i * 4 + 3] = v.w;
        }
        float acc = 0.f;
        #pragma unroll
        for (int k = 0; k < HH; k++) {
            float hk = __shfl_sync(0xffffffffu, h[((k >> 7) << 2) + (k & 3)], (k >> 2) & 31);
            acc += hk * __ldg(&W2[k * TT + colIdx]);
        }
        if (lane < TT) g_E[(size_t)row * TT + lane] = acc + bias;
    }
}

// ============================================================================
// CRF: one warp per batch element. numerator + forward scan (log semiring)
// Handles mask delivered as float32 / int32 / packed bytes, labels int64/int32.
// ============================================================================
__global__ void crf_kernel(const float* __restrict__ start_t,
                           const float* __restrict__ end_t,
                           const float* __restrict__ trans,
                           const void*  __restrict__ labels_raw,
                           const void*  __restrict__ mask_raw)
{
    __shared__ float trans_sh[TT * TT];
    __shared__ float alpha_sh[32];
    __shared__ unsigned char msh[SS];

    const int b = blockIdx.x;
    const int lane = threadIdx.x;
    const unsigned full = 0xffffffffu;

    for (int i = lane; i < TT * TT; i += 32) trans_sh[i] = trans[i];

    // ---- detect label dtype: int64 vs int32 ----
    const int* li = (const int*)labels_raw;
    unsigned ball = __ballot_sync(full, li[2 * lane + 1] == 0);
    const int lstride = (ball == full) ? 2 : 1;

    // ---- detect mask encoding ----
    const unsigned* mw = (const unsigned*)mask_raw;
    unsigned any_high = 0, any_float = 0;
    for (int i = lane; i < 256; i += 32) {
        unsigned wv = mw[i];
        any_float |= (wv == 0x3F800000u);
        any_high  |= (wv & 0xFFFFFF00u) && (wv != 0x3F800000u);
    }
    const bool is_float = __ballot_sync(full, any_float != 0) != 0;
    const bool is_byte  = !is_float && (__ballot_sync(full, any_high != 0) != 0);

    const int base = b * SS;

    for (int t = lane; t < SS; t += 32) {
        unsigned char mv;
        if (is_float)      mv = (((const float*)mask_raw)[base + t] != 0.f);
        else if (is_byte)  mv = (((const unsigned char*)mask_raw)[base + t] != 0);
        else               mv = (((const int*)mask_raw)[base + t] != 0);
        msh[t] = mv;
    }
    __syncwarp();

    const float* Eb = g_E + (size_t)base * TT;

    // ---- numerator ----
    float acc = 0.f;
    int cnt = 0;
    for (int t = lane; t < SS; t += 32) cnt += msh[t] ? 1 : 0;
    for (int t = 1 + lane; t < SS; t += 32) {
        if (msh[t]) {
            int lt = li[(base + t) * lstride];
            int lp = li[(base + t - 1) * lstride];
            acc += trans_sh[lp * TT + lt] + Eb[t * TT + lt];
        }
    }
    #pragma unroll
    for (int off = 16; off > 0; off >>= 1) {
        acc += __shfl_xor_sync(full, acc, off);
        cnt += __shfl_xor_sync(full, cnt, off);
    }

    // ---- forward scan ----
    float alpha = (lane < TT) ? (start_t[lane] + Eb[lane]) : -INFINITY;

    float e_next = (lane < TT) ? Eb[1 * TT + lane] : 0.f;
    unsigned char m_next = msh[1];

    for (int t = 1; t < SS; t++) {
        float e_cur = e_next;
        unsigned char m_cur = m_next;
        if (t + 1 < SS) {
            e_next = (lane < TT) ? Eb[(t + 1) * TT + lane] : 0.f;
            m_next = msh[t + 1];
        }
        alpha_sh[lane] = alpha;
        __syncwarp();
        float M = __shfl_sync(full, alpha, 0);
        float s = 0.f;
        if (lane < TT) {
            #pragma unroll
            for (int i = 0; i < TT; i++)
                s += __expf(alpha_sh[i] - M + trans_sh[i * TT + lane]);
        }
        float nv = e_cur + M + __logf(s);
        if (lane < TT && m_cur) alpha = nv;
        __syncwarp();
    }

    float v = (lane < TT) ? (alpha + end_t[lane]) : -INFINITY;
    float M2 = v;
    #pragma unroll
    for (int off = 16; off > 0; off >>= 1)
        M2 = fmaxf(M2, __shfl_xor_sync(full, M2, off));
    float s2 = (lane < TT) ? __expf(v - M2) : 0.f;
    #pragma unroll
    for (int off = 16; off > 0; off >>= 1)
        s2 += __shfl_xor_sync(full, s2, off);

    if (lane == 0) {
        int lab0 = li[base * lstride];
        float score0 = start_t[lab0] + Eb[lab0];
        int last_idx = cnt - 1;
        int last_tag = li[(base + last_idx) * lstride];
        float numerator = score0 + acc + end_t[last_tag];
        float logZ = M2 + __logf(s2);
        g_ll[b] = numerator - logZ;
    }
}

// ============================================================================
// finalize: out = -mean(ll)
// ============================================================================
__global__ void finalize_kernel(float* __restrict__ out)
{
    __shared__ float sbuf[2];
    const int l = threadIdx.x; // 64 threads
    float v = g_ll[l];
    #pragma unroll
    for (int off = 16; off > 0; off >>= 1)
        v += __shfl_xor_sync(0xffffffffu, v, off);
    if ((l & 31) == 0) sbuf[l >> 5] = v;
    __syncthreads();
    if (l == 0) out[0] = -(sbuf[0] + sbuf[1]) / (float)BB;
}

// ============================================================================
// launch
// ============================================================================
extern "C" void kernel_launch(void* const* d_in, const int* in_sizes, int n_in,
                              void* d_out, int out_size)
{
    const float* X       = (const float*)d_in[0];
    const float* W1      = (const float*)d_in[1];
    const float* b1      = (const float*)d_in[2];
    const float* W2      = (const float*)d_in[3];
    const float* b2      = (const float*)d_in[4];
    const float* start_t = (const float*)d_in[5];
    const float* end_t   = (const float*)d_in[6];
    const float* trans   = (const float*)d_in[7];
    const void*  labels  = d_in[8];
    const void*  mask    = d_in[9];
    float* out = (float*)d_out;

    // bf16 conversion passes
    convert_X_kernel<<<(MROWS * DD / 8) / 256, 256>>>(X);
    convert_W1_kernel<<<(DD * HH / 8) / 256, 256>>>(W1);

    // GEMM1 (tensor cores) + gelu
    dim3 g1(HH / 128, MROWS / 128);
    gemm1_bf16_kernel<<<g1, 256>>>(b1);

    gemm2_kernel<<<1024, 256>>>(W2, b2);

    crf_kernel<<<BB, 32>>>(start_t, end_t, trans, labels, mask);

    finalize_kernel<<<1, 64>>>(out);
}

// round 4
// speedup vs baseline: 4.0030x; 2.2251x over previous
#include <cuda_runtime.h>
#include <cuda_bf16.h>
#include <math.h>
#include <stdint.h>

// Problem constants
#define BB   64
#define SS   512
#define DD   1024
#define HH   512
#define TT   25
#define MROWS (BB*SS)          // 32768

// -------- scratch (allocation-free: __device__ globals) --------
__device__ uint4 g_Xs[(size_t)MROWS * DD / 8];   // 64 MB bf16 X, tiled+swizzled
__device__ uint4 g_W1s[(size_t)DD * HH / 8];     // 1 MB bf16 W1, tiled+swizzled
__device__ float g_Ep[4][(size_t)MROWS * TT];    // split-K emission partials
__device__ float g_E[(size_t)MROWS * TT + 32];   // emissions (+pad)
__device__ float g_ll[BB];                       // per-batch log-likelihood

// ============================================================================
// Convert X -> bf16 tiles [mtile 256][ktile 32][row 128][chunk 4 x 16B],
// chunk swizzled: c' = c ^ (r&3) ^ ((r>>2)&1)
// ============================================================================
__global__ __launch_bounds__(256)
void convert_X_kernel(const float* __restrict__ X)
{
    int id = blockIdx.x * 256 + threadIdx.x;      // one 16B output chunk
    int tile   = id >> 9;                          // 512 chunks per tile
    int within = id & 511;
    int r  = within >> 2;
    int cp = within & 3;
    int mtile = tile >> 5;
    int ktile = tile & 31;
    int sw = (r & 3) ^ ((r >> 2) & 1);
    int c  = cp ^ sw;
    int m = mtile * 128 + r;
    int k = ktile * 32 + c * 8;
    const float4* src = (const float4*)(X + (size_t)m * DD + k);
    float4 x0 = src[0], x1 = src[1];
    __nv_bfloat162 p0 = __floats2bfloat162_rn(x0.x, x0.y);
    __nv_bfloat162 p1 = __floats2bfloat162_rn(x0.z, x0.w);
    __nv_bfloat162 p2 = __floats2bfloat162_rn(x1.x, x1.y);
    __nv_bfloat162 p3 = __floats2bfloat162_rn(x1.z, x1.w);
    uint4 out;
    out.x = *(uint32_t*)&p0; out.y = *(uint32_t*)&p1;
    out.z = *(uint32_t*)&p2; out.w = *(uint32_t*)&p3;
    g_Xs[id] = out;
}

// ============================================================================
// Convert W1 -> bf16 tiles [ktile 32][ntile 4][krow 32][chunk 16 x 16B],
// chunk swizzled: c' = c ^ (k&7)
// ============================================================================
__global__ __launch_bounds__(256)
void convert_W1_kernel(const float* __restrict__ W1)
{
    int id = blockIdx.x * 256 + threadIdx.x;      // one 16B output chunk
    int tile   = id >> 9;
    int within = id & 511;
    int k  = within >> 4;
    int cp = within & 15;
    int ktile = tile >> 2;
    int ntile = tile & 3;
    int c = cp ^ (k & 7);
    int krow = ktile * 32 + k;
    int n = ntile * 128 + c * 8;
    const float4* src = (const float4*)(W1 + (size_t)krow * HH + n);
    float4 x0 = src[0], x1 = src[1];
    __nv_bfloat162 p0 = __floats2bfloat162_rn(x0.x, x0.y);
    __nv_bfloat162 p1 = __floats2bfloat162_rn(x0.z, x0.w);
    __nv_bfloat162 p2 = __floats2bfloat162_rn(x1.x, x1.y);
    __nv_bfloat162 p3 = __floats2bfloat162_rn(x1.z, x1.w);
    uint4 out;
    out.x = *(uint32_t*)&p0; out.y = *(uint32_t*)&p1;
    out.z = *(uint32_t*)&p2; out.w = *(uint32_t*)&p3;
    g_W1s[id] = out;
}

// ============================================================================
// GEMM1 (tensor cores): H = gelu(X @ W1 + b1), fused GEMM2 partials
// 128x128x32 tiles, 3-stage cp.async pipeline, mma.sync m16n8k16 bf16
// Epilogue: gelu -> bf16 smem tile -> mma with W2 chunk -> g_Ep[ntile]
// ============================================================================
#define STAGES 3
#define NIT (DD / 32)   // 32 k-iterations

__device__ __forceinline__ void cp_async16(uint32_t saddr, const void* gaddr) {
    asm volatile("cp.async.cg.shared.global [%0], [%1], 16;\n"
                 :: "r"(saddr), "l"(gaddr));
}
__device__ __forceinline__ void cp_commit() {
    asm volatile("cp.async.commit_group;\n");
}
__device__ __forceinline__ void cp_wait2() {
    asm volatile("cp.async.wait_group 2;\n");
}
__device__ __forceinline__ void ldmatrix_x4(uint32_t* r, uint32_t addr) {
    asm volatile("ldmatrix.sync.aligned.m8n8.x4.shared.b16 {%0,%1,%2,%3}, [%4];"
                 : "=r"(r[0]), "=r"(r[1]), "=r"(r[2]), "=r"(r[3]) : "r"(addr));
}
__device__ __forceinline__ void ldmatrix_x4_trans(uint32_t* r, uint32_t addr) {
    asm volatile("ldmatrix.sync.aligned.m8n8.x4.trans.shared.b16 {%0,%1,%2,%3}, [%4];"
                 : "=r"(r[0]), "=r"(r[1]), "=r"(r[2]), "=r"(r[3]) : "r"(addr));
}
__device__ __forceinline__ void mma_bf16(float* c, const uint32_t* a,
                                         uint32_t b0, uint32_t b1) {
    asm volatile("mma.sync.aligned.m16n8k16.row.col.f32.bf16.bf16.f32 "
                 "{%0,%1,%2,%3},{%4,%5,%6,%7},{%8,%9},{%0,%1,%2,%3};"
                 : "+f"(c[0]), "+f"(c[1]), "+f"(c[2]), "+f"(c[3])
                 : "r"(a[0]), "r"(a[1]), "r"(a[2]), "r"(a[3]), "r"(b0), "r"(b1));
}

__global__ __launch_bounds__(256)
void gemm1_fused_kernel(const float* __restrict__ b1,
                        const float* __restrict__ W2)
{
    __shared__ __align__(16) unsigned char sm[49152];

    const int tid  = threadIdx.x;
    const int lane = tid & 31;
    const int w    = tid >> 5;
    const int wm   = w & 3;    // 0..3 (m)
    const int wn   = w >> 2;   // 0..1 (n)
    const int ntile = blockIdx.x;   // 0..3
    const int mtile = blockIdx.y;   // 0..255

    uint32_t sbase = (uint32_t)__cvta_generic_to_shared(&sm[0]);
    uint32_t sA0 = sbase;              // 3 stages x 8KB
    uint32_t sB0 = sbase + 24576;      // 3 stages x 8KB

    const int cid0 = tid;
    const int cid1 = tid + 256;

    auto issue = [&](int stage, int it) {
        const uint4* gA = g_Xs + ((size_t)(mtile * 32 + it)) * 512;
        const uint4* gB = g_W1s + ((size_t)(it * 4 + ntile)) * 512;
        uint32_t sa = sA0 + stage * 8192;
        uint32_t sb = sB0 + stage * 8192;
        cp_async16(sa + cid0 * 16, gA + cid0);
        cp_async16(sa + cid1 * 16, gA + cid1);
        cp_async16(sb + cid0 * 16, gB + cid0);
        cp_async16(sb + cid1 * 16, gB + cid1);
    };

    // --- lane-dependent ldmatrix offsets (mainloop) ---
    int rA0 = wm * 32 + (lane & 15);
    int rA1 = rA0 + 16;
    int swzA0 = (rA0 & 3) ^ ((rA0 >> 2) & 1);
    int swzA1 = (rA1 & 3) ^ ((rA1 >> 2) & 1);
    int caBase = lane >> 4;
    int kBoff = lane & 15;
    int cbBase = wn * 8 + (lane >> 4);
    int kx = lane & 7;

    float c[2][8][4];
    #pragma unroll
    for (int im = 0; im < 2; im++)
        #pragma unroll
        for (int in = 0; in < 8; in++)
            #pragma unroll
            for (int r = 0; r < 4; r++) c[im][in][r] = 0.f;

    issue(0, 0); cp_commit();
    issue(1, 1); cp_commit();

    for (int it = 0; it < NIT; ++it) {
        if (it + 2 < NIT) issue((it + 2) % STAGES, it + 2);
        cp_commit();
        cp_wait2();
        __syncthreads();

        const int st = it % STAGES;
        uint32_t abase = sA0 + st * 8192;
        uint32_t bbase = sB0 + st * 8192;

        #pragma unroll
        for (int s = 0; s < 2; s++) {
            uint32_t a[2][4];
            {
                int ch0 = (2 * s + caBase) ^ swzA0;
                int ch1 = (2 * s + caBase) ^ swzA1;
                ldmatrix_x4(a[0], abase + rA0 * 64 + ch0 * 16);
                ldmatrix_x4(a[1], abase + rA1 * 64 + ch1 * 16);
            }
            uint32_t bt[4][4];
            #pragma unroll
            for (int inb = 0; inb < 4; inb++) {
                int ch = (cbBase + inb * 2) ^ kx;
                ldmatrix_x4_trans(bt[inb], bbase + (16 * s + kBoff) * 256 + ch * 16);
            }
            #pragma unroll
            for (int im = 0; im < 2; im++)
                #pragma unroll
                for (int in = 0; in < 8; in++) {
                    uint32_t b0 = bt[in >> 1][(in & 1) * 2];
                    uint32_t b1r = bt[in >> 1][(in & 1) * 2 + 1];
                    mma_bf16(c[im][in], a[im], b0, b1r);
                }
        }
        __syncthreads();
    }

    // ======================= fused epilogue =======================
    // 1) gelu + bias, pack bf16, store 128x128 H tile into smem.
    //    Layout: row-major 256B rows; 16B chunk swizzle ch' = ch ^ (row&7)
    //    (for chunk indices 0..15; XOR touches only low 3 bits).
    const int g  = lane >> 2;
    const int tg = lane & 3;
    const uint32_t hbase = sbase;              // reuse stage mem: 32KB
    const uint32_t w2b   = sbase + 32768;      // W2 chunk: 128 rows x 80B
    {
        const int nbase = ntile * 128 + wn * 64;
        #pragma unroll
        for (int im = 0; im < 2; im++) {
            #pragma unroll
            for (int in = 0; in < 8; in++) {
                int col = nbase + in * 8 + tg * 2;
                float bias0 = __ldg(&b1[col]);
                float bias1 = __ldg(&b1[col + 1]);
                #pragma unroll
                for (int h = 0; h < 2; h++) {
                    int row = wm * 32 + im * 16 + g + 8 * h;  // row in tile
                    float v0 = c[im][in][2 * h]     + bias0;
                    float v1 = c[im][in][2 * h + 1] + bias1;
                    v0 = 0.5f * v0 * (1.0f + erff(v0 * 0.70710678118654752f));
                    v1 = 0.5f * v1 * (1.0f + erff(v1 * 0.70710678118654752f));
                    __nv_bfloat162 p = __floats2bfloat162_rn(v0, v1);
                    int physu = ((in ^ (row & 7)) + 8 * wn) * 4 + tg;
                    uint32_t addr = hbase + row * 256 + physu * 4;
                    asm volatile("st.shared.b32 [%0], %1;\n"
                                 :: "r"(addr), "r"(*(uint32_t*)&p));
                }
            }
        }
    }
    // 2) load W2 chunk [128 x 25] -> bf16 smem [128 rows x 80B stride, 32 cols pad]
    for (int idx = tid; idx < 128 * 32; idx += 256) {
        int r  = idx >> 5;
        int cc = idx & 31;
        float v = (cc < TT) ? __ldg(&W2[(size_t)(ntile * 128 + r) * TT + cc]) : 0.f;
        __nv_bfloat16 bv = __float2bfloat16(v);
        uint32_t addr = w2b + r * 80 + cc * 2;
        asm volatile("st.shared.b16 [%0], %1;\n"
                     :: "r"(addr), "h"(*(uint16_t*)&bv));
    }
    __syncthreads();

    // 3) second MMA: Ep = Htile[128x128] @ W2chunk[128x32]
    //    warp w handles rows w*16..w*16+16
    {
        float e[4][4];
        #pragma unroll
        for (int j = 0; j < 4; j++)
            #pragma unroll
            for (int r = 0; r < 4; r++) e[j][r] = 0.f;

        const int arow = w * 16 + (lane & 15);
        const int asw  = arow & 7;

        #pragma unroll
        for (int k0 = 0; k0 < 128; k0 += 16) {
            uint32_t a[4];
            int ch = ((k0 >> 3) + (lane >> 4)) ^ asw;
            ldmatrix_x4(a, hbase + arow * 256 + ch * 16);
            #pragma unroll
            for (int nt2 = 0; nt2 < 2; nt2++) {
                uint32_t bt[4];
                uint32_t baddr = w2b + (k0 + (lane & 15)) * 80
                               + ((lane >> 4) + 2 * nt2) * 16;
                ldmatrix_x4_trans(bt, baddr);
                mma_bf16(e[nt2 * 2 + 0], a, bt[0], bt[1]);
                mma_bf16(e[nt2 * 2 + 1], a, bt[2], bt[3]);
            }
        }

        // 4) write partials (split-K, deterministic)
        float* Ep = g_Ep[ntile];
        #pragma unroll
        for (int j = 0; j < 4; j++) {
            int col = j * 8 + tg * 2;
            #pragma unroll
            for (int h2 = 0; h2 < 2; h2++) {
                int row = mtile * 128 + w * 16 + g + 8 * h2;
                if (col < TT)     Ep[(size_t)row * TT + col]     = e[j][2 * h2];
                if (col + 1 < TT) Ep[(size_t)row * TT + col + 1] = e[j][2 * h2 + 1];
            }
        }
    }
}

// ============================================================================
// reduce: E = sum_k Ep[k] + b2
// ============================================================================
__global__ __launch_bounds__(256)
void reduce_E_kernel(const float* __restrict__ b2)
{
    int i = blockIdx.x * 256 + threadIdx.x;
    if (i < MROWS * TT) {
        float s = g_Ep[0][i] + g_Ep[1][i] + g_Ep[2][i] + g_Ep[3][i];
        g_E[i] = s + __ldg(&b2[i % TT]);
    }
}

// ============================================================================
// CRF: one warp per batch element. numerator + forward scan (log semiring)
// Handles mask delivered as float32 / int32 / packed bytes, labels int64/int32.
// ============================================================================
__global__ void crf_kernel(const float* __restrict__ start_t,
                           const float* __restrict__ end_t,
                           const float* __restrict__ trans,
                           const void*  __restrict__ labels_raw,
                           const void*  __restrict__ mask_raw)
{
    __shared__ float trans_sh[TT * TT];
    __shared__ float alpha_sh[32];
    __shared__ unsigned char msh[SS];

    const int b = blockIdx.x;
    const int lane = threadIdx.x;
    const unsigned full = 0xffffffffu;

    for (int i = lane; i < TT * TT; i += 32) trans_sh[i] = trans[i];

    // ---- detect label dtype: int64 vs int32 ----
    const int* li = (const int*)labels_raw;
    unsigned ball = __ballot_sync(full, li[2 * lane + 1] == 0);
    const int lstride = (ball == full) ? 2 : 1;

    // ---- detect mask encoding ----
    const unsigned* mw = (const unsigned*)mask_raw;
    unsigned any_high = 0, any_float = 0;
    for (int i = lane; i < 256; i += 32) {
        unsigned wv = mw[i];
        any_float |= (wv == 0x3F800000u);
        any_high  |= (wv & 0xFFFFFF00u) && (wv != 0x3F800000u);
    }
    const bool is_float = __ballot_sync(full, any_float != 0) != 0;
    const bool is_byte  = !is_float && (__ballot_sync(full, any_high != 0) != 0);

    const int base = b * SS;

    for (int t = lane; t < SS; t += 32) {
        unsigned char mv;
        if (is_float)      mv = (((const float*)mask_raw)[base + t] != 0.f);
        else if (is_byte)  mv = (((const unsigned char*)mask_raw)[base + t] != 0);
        else               mv = (((const int*)mask_raw)[base + t] != 0);
        msh[t] = mv;
    }
    __syncwarp();

    const float* Eb = g_E + (size_t)base * TT;

    // ---- numerator ----
    float acc = 0.f;
    int cnt = 0;
    for (int t = lane; t < SS; t += 32) cnt += msh[t] ? 1 : 0;
    for (int t = 1 + lane; t < SS; t += 32) {
        if (msh[t]) {
            int lt = li[(base + t) * lstride];
            int lp = li[(base + t - 1) * lstride];
            acc += trans_sh[lp * TT + lt] + Eb[t * TT + lt];
        }
    }
    #pragma unroll
    for (int off = 16; off > 0; off >>= 1) {
        acc += __shfl_xor_sync(full, acc, off);
        cnt += __shfl_xor_sync(full, cnt, off);
    }

    // ---- forward scan ----
    float alpha = (lane < TT) ? (start_t[lane] + Eb[lane]) : -INFINITY;

    float e_next = (lane < TT) ? Eb[1 * TT + lane] : 0.f;
    unsigned char m_next = msh[1];

    for (int t = 1; t < SS; t++) {
        float e_cur = e_next;
        unsigned char m_cur = m_next;
        if (t + 1 < SS) {
            e_next = (lane < TT) ? Eb[(t + 1) * TT + lane] : 0.f;
            m_next = msh[t + 1];
        }
        alpha_sh[lane] = alpha;
        __syncwarp();
        float M = __shfl_sync(full, alpha, 0);
        float s = 0.f;
        if (lane < TT) {
            #pragma unroll
            for (int i = 0; i < TT; i++)
                s += __expf(alpha_sh[i] - M + trans_sh[i * TT + lane]);
        }
        float nv = e_cur + M + __logf(s);
        if (lane < TT && m_cur) alpha = nv;
        __syncwarp();
    }

    float v = (lane < TT) ? (alpha + end_t[lane]) : -INFINITY;
    float M2 = v;
    #pragma unroll
    for (int off = 16; off > 0; off >>= 1)
        M2 = fmaxf(M2, __shfl_xor_sync(full, M2, off));
    float s2 = (lane < TT) ? __expf(v - M2) : 0.f;
    #pragma unroll
    for (int off = 16; off > 0; off >>= 1)
        s2 += __shfl_xor_sync(full, s2, off);

    if (lane == 0) {
        int lab0 = li[base * lstride];
        float score0 = start_t[lab0] + Eb[lab0];
        int last_idx = cnt - 1;
        int last_tag = li[(base + last_idx) * lstride];
        float numerator = score0 + acc + end_t[last_tag];
        float logZ = M2 + __logf(s2);
        g_ll[b] = numerator - logZ;
    }
}

// ============================================================================
// finalize: out = -mean(ll)
// ============================================================================
__global__ void finalize_kernel(float* __restrict__ out)
{
    __shared__ float sbuf[2];
    const int l = threadIdx.x; // 64 threads
    float v = g_ll[l];
    #pragma unroll
    for (int off = 16; off > 0; off >>= 1)
        v += __shfl_xor_sync(0xffffffffu, v, off);
    if ((l & 31) == 0) sbuf[l >> 5] = v;
    __syncthreads();
    if (l == 0) out[0] = -(sbuf[0] + sbuf[1]) / (float)BB;
}

// ============================================================================
// launch
// ============================================================================
extern "C" void kernel_launch(void* const* d_in, const int* in_sizes, int n_in,
                              void* d_out, int out_size)
{
    const float* X       = (const float*)d_in[0];
    const float* W1      = (const float*)d_in[1];
    const float* b1      = (const float*)d_in[2];
    const float* W2      = (const float*)d_in[3];
    const float* b2      = (const float*)d_in[4];
    const float* start_t = (const float*)d_in[5];
    const float* end_t   = (const float*)d_in[6];
    const float* trans   = (const float*)d_in[7];
    const void*  labels  = d_in[8];
    const void*  mask    = d_in[9];
    float* out = (float*)d_out;

    // bf16 conversion passes
    convert_X_kernel<<<(MROWS * DD / 8) / 256, 256>>>(X);
    convert_W1_kernel<<<(DD * HH / 8) / 256, 256>>>(W1);

    // GEMM1 (tensor cores) + gelu + fused GEMM2 partials
    dim3 g1(HH / 128, MROWS / 128);
    gemm1_fused_kernel<<<g1, 256>>>(b1, W2);

    // E = sum partials + b2
    reduce_E_kernel<<<(MROWS * TT + 255) / 256, 256>>>(b2);

    crf_kernel<<<BB, 32>>>(start_t, end_t, trans, labels, mask);

    finalize_kernel<<<1, 64>>>(out);
}

// round 5
// speedup vs baseline: 4.6951x; 1.1729x over previous
#include <cuda_runtime.h>
#include <cuda_bf16.h>
#include <math.h>
#include <stdint.h>

// Problem constants
#define BB   64
#define SS   512
#define DD   1024
#define HH   512
#define TT   25
#define MROWS (BB*SS)          // 32768

// -------- scratch (allocation-free: __device__ globals) --------
__device__ uint4 g_Xs[(size_t)MROWS * DD / 8];   // 64 MB bf16 X, tiled+swizzled
__device__ uint4 g_W1s[(size_t)DD * HH / 8];     // 1 MB bf16 W1, tiled+swizzled
__device__ float g_Ep[4][(size_t)MROWS * TT];    // split-K emission partials
__device__ float g_E[(size_t)MROWS * TT + 32];   // emissions (+pad)
__device__ float g_ll[BB];                       // per-batch log-likelihood

// ============================================================================
// Convert X -> bf16 tiles [mtile 256][ktile 32][row 128][chunk 4 x 16B],
// chunk swizzled: c' = c ^ (r&3) ^ ((r>>2)&1)
// ============================================================================
__global__ __launch_bounds__(256)
void convert_X_kernel(const float* __restrict__ X)
{
    int id = blockIdx.x * 256 + threadIdx.x;      // one 16B output chunk
    int tile   = id >> 9;                          // 512 chunks per tile
    int within = id & 511;
    int r  = within >> 2;
    int cp = within & 3;
    int mtile = tile >> 5;
    int ktile = tile & 31;
    int sw = (r & 3) ^ ((r >> 2) & 1);
    int c  = cp ^ sw;
    int m = mtile * 128 + r;
    int k = ktile * 32 + c * 8;
    const float4* src = (const float4*)(X + (size_t)m * DD + k);
    float4 x0 = src[0], x1 = src[1];
    __nv_bfloat162 p0 = __floats2bfloat162_rn(x0.x, x0.y);
    __nv_bfloat162 p1 = __floats2bfloat162_rn(x0.z, x0.w);
    __nv_bfloat162 p2 = __floats2bfloat162_rn(x1.x, x1.y);
    __nv_bfloat162 p3 = __floats2bfloat162_rn(x1.z, x1.w);
    uint4 out;
    out.x = *(uint32_t*)&p0; out.y = *(uint32_t*)&p1;
    out.z = *(uint32_t*)&p2; out.w = *(uint32_t*)&p3;
    g_Xs[id] = out;
}

// ============================================================================
// Convert W1 -> bf16 tiles [ktile 32][ntile 4][krow 32][chunk 16 x 16B],
// chunk swizzled: c' = c ^ (k&7)
// ============================================================================
__global__ __launch_bounds__(256)
void convert_W1_kernel(const float* __restrict__ W1)
{
    int id = blockIdx.x * 256 + threadIdx.x;      // one 16B output chunk
    int tile   = id >> 9;
    int within = id & 511;
    int k  = within >> 4;
    int cp = within & 15;
    int ktile = tile >> 2;
    int ntile = tile & 3;
    int c = cp ^ (k & 7);
    int krow = ktile * 32 + k;
    int n = ntile * 128 + c * 8;
    const float4* src = (const float4*)(W1 + (size_t)krow * HH + n);
    float4 x0 = src[0], x1 = src[1];
    __nv_bfloat162 p0 = __floats2bfloat162_rn(x0.x, x0.y);
    __nv_bfloat162 p1 = __floats2bfloat162_rn(x0.z, x0.w);
    __nv_bfloat162 p2 = __floats2bfloat162_rn(x1.x, x1.y);
    __nv_bfloat162 p3 = __floats2bfloat162_rn(x1.z, x1.w);
    uint4 out;
    out.x = *(uint32_t*)&p0; out.y = *(uint32_t*)&p1;
    out.z = *(uint32_t*)&p2; out.w = *(uint32_t*)&p3;
    g_W1s[id] = out;
}

// ============================================================================
// GEMM1 (tensor cores): H = gelu(X @ W1 + b1), fused GEMM2 partials
// 128x128x32 tiles, 3-stage cp.async pipeline, mma.sync m16n8k16 bf16
// Epilogue: gelu -> bf16 smem tile -> mma with W2 chunk -> g_Ep[ntile]
// ============================================================================
#define STAGES 3
#define NIT (DD / 32)   // 32 k-iterations

__device__ __forceinline__ void cp_async16(uint32_t saddr, const void* gaddr) {
    asm volatile("cp.async.cg.shared.global [%0], [%1], 16;\n"
                 :: "r"(saddr), "l"(gaddr));
}
__device__ __forceinline__ void cp_commit() {
    asm volatile("cp.async.commit_group;\n");
}
__device__ __forceinline__ void cp_wait2() {
    asm volatile("cp.async.wait_group 2;\n");
}
__device__ __forceinline__ void ldmatrix_x4(uint32_t* r, uint32_t addr) {
    asm volatile("ldmatrix.sync.aligned.m8n8.x4.shared.b16 {%0,%1,%2,%3}, [%4];"
                 : "=r"(r[0]), "=r"(r[1]), "=r"(r[2]), "=r"(r[3]) : "r"(addr));
}
__device__ __forceinline__ void ldmatrix_x4_trans(uint32_t* r, uint32_t addr) {
    asm volatile("ldmatrix.sync.aligned.m8n8.x4.trans.shared.b16 {%0,%1,%2,%3}, [%4];"
                 : "=r"(r[0]), "=r"(r[1]), "=r"(r[2]), "=r"(r[3]) : "r"(addr));
}
__device__ __forceinline__ void mma_bf16(float* c, const uint32_t* a,
                                         uint32_t b0, uint32_t b1) {
    asm volatile("mma.sync.aligned.m16n8k16.row.col.f32.bf16.bf16.f32 "
                 "{%0,%1,%2,%3},{%4,%5,%6,%7},{%8,%9},{%0,%1,%2,%3};"
                 : "+f"(c[0]), "+f"(c[1]), "+f"(c[2]), "+f"(c[3])
                 : "r"(a[0]), "r"(a[1]), "r"(a[2]), "r"(a[3]), "r"(b0), "r"(b1));
}

__global__ __launch_bounds__(256)
void gemm1_fused_kernel(const float* __restrict__ b1,
                        const float* __restrict__ W2)
{
    __shared__ __align__(16) unsigned char sm[49152];

    const int tid  = threadIdx.x;
    const int lane = tid & 31;
    const int w    = tid >> 5;
    const int wm   = w & 3;    // 0..3 (m)
    const int wn   = w >> 2;   // 0..1 (n)
    const int ntile = blockIdx.x;   // 0..3
    const int mtile = blockIdx.y;   // 0..255

    uint32_t sbase = (uint32_t)__cvta_generic_to_shared(&sm[0]);
    uint32_t sA0 = sbase;              // 3 stages x 8KB
    uint32_t sB0 = sbase + 24576;      // 3 stages x 8KB

    const int cid0 = tid;
    const int cid1 = tid + 256;

    auto issue = [&](int stage, int it) {
        const uint4* gA = g_Xs + ((size_t)(mtile * 32 + it)) * 512;
        const uint4* gB = g_W1s + ((size_t)(it * 4 + ntile)) * 512;
        uint32_t sa = sA0 + stage * 8192;
        uint32_t sb = sB0 + stage * 8192;
        cp_async16(sa + cid0 * 16, gA + cid0);
        cp_async16(sa + cid1 * 16, gA + cid1);
        cp_async16(sb + cid0 * 16, gB + cid0);
        cp_async16(sb + cid1 * 16, gB + cid1);
    };

    // --- lane-dependent ldmatrix offsets (mainloop) ---
    int rA0 = wm * 32 + (lane & 15);
    int rA1 = rA0 + 16;
    int swzA0 = (rA0 & 3) ^ ((rA0 >> 2) & 1);
    int swzA1 = (rA1 & 3) ^ ((rA1 >> 2) & 1);
    int caBase = lane >> 4;
    int kBoff = lane & 15;
    int cbBase = wn * 8 + (lane >> 4);
    int kx = lane & 7;

    float c[2][8][4];
    #pragma unroll
    for (int im = 0; im < 2; im++)
        #pragma unroll
        for (int in = 0; in < 8; in++)
            #pragma unroll
            for (int r = 0; r < 4; r++) c[im][in][r] = 0.f;

    issue(0, 0); cp_commit();
    issue(1, 1); cp_commit();

    for (int it = 0; it < NIT; ++it) {
        if (it + 2 < NIT) issue((it + 2) % STAGES, it + 2);
        cp_commit();
        cp_wait2();
        __syncthreads();

        const int st = it % STAGES;
        uint32_t abase = sA0 + st * 8192;
        uint32_t bbase = sB0 + st * 8192;

        #pragma unroll
        for (int s = 0; s < 2; s++) {
            uint32_t a[2][4];
            {
                int ch0 = (2 * s + caBase) ^ swzA0;
                int ch1 = (2 * s + caBase) ^ swzA1;
                ldmatrix_x4(a[0], abase + rA0 * 64 + ch0 * 16);
                ldmatrix_x4(a[1], abase + rA1 * 64 + ch1 * 16);
            }
            uint32_t bt[4][4];
            #pragma unroll
            for (int inb = 0; inb < 4; inb++) {
                int ch = (cbBase + inb * 2) ^ kx;
                ldmatrix_x4_trans(bt[inb], bbase + (16 * s + kBoff) * 256 + ch * 16);
            }
            #pragma unroll
            for (int im = 0; im < 2; im++)
                #pragma unroll
                for (int in = 0; in < 8; in++) {
                    uint32_t b0 = bt[in >> 1][(in & 1) * 2];
                    uint32_t b1r = bt[in >> 1][(in & 1) * 2 + 1];
                    mma_bf16(c[im][in], a[im], b0, b1r);
                }
        }
        __syncthreads();
    }

    // ======================= fused epilogue =======================
    const int g  = lane >> 2;
    const int tg = lane & 3;
    const uint32_t hbase = sbase;              // reuse stage mem: 32KB
    const uint32_t w2b   = sbase + 32768;      // W2 chunk: 128 rows x 80B
    {
        const int nbase = ntile * 128 + wn * 64;
        #pragma unroll
        for (int im = 0; im < 2; im++) {
            #pragma unroll
            for (int in = 0; in < 8; in++) {
                int col = nbase + in * 8 + tg * 2;
                float bias0 = __ldg(&b1[col]);
                float bias1 = __ldg(&b1[col + 1]);
                #pragma unroll
                for (int h = 0; h < 2; h++) {
                    int row = wm * 32 + im * 16 + g + 8 * h;  // row in tile
                    float v0 = c[im][in][2 * h]     + bias0;
                    float v1 = c[im][in][2 * h + 1] + bias1;
                    v0 = 0.5f * v0 * (1.0f + erff(v0 * 0.70710678118654752f));
                    v1 = 0.5f * v1 * (1.0f + erff(v1 * 0.70710678118654752f));
                    __nv_bfloat162 p = __floats2bfloat162_rn(v0, v1);
                    int physu = ((in ^ (row & 7)) + 8 * wn) * 4 + tg;
                    uint32_t addr = hbase + row * 256 + physu * 4;
                    asm volatile("st.shared.b32 [%0], %1;\n"
                                 :: "r"(addr), "r"(*(uint32_t*)&p));
                }
            }
        }
    }
    // W2 chunk [128 x 25] -> bf16 smem [128 rows x 80B stride, 32 cols pad]
    for (int idx = tid; idx < 128 * 32; idx += 256) {
        int r  = idx >> 5;
        int cc = idx & 31;
        float v = (cc < TT) ? __ldg(&W2[(size_t)(ntile * 128 + r) * TT + cc]) : 0.f;
        __nv_bfloat16 bv = __float2bfloat16(v);
        uint32_t addr = w2b + r * 80 + cc * 2;
        asm volatile("st.shared.b16 [%0], %1;\n"
                     :: "r"(addr), "h"(*(uint16_t*)&bv));
    }
    __syncthreads();

    // second MMA: Ep = Htile[128x128] @ W2chunk[128x32]
    {
        float e[4][4];
        #pragma unroll
        for (int j = 0; j < 4; j++)
            #pragma unroll
            for (int r = 0; r < 4; r++) e[j][r] = 0.f;

        const int arow = w * 16 + (lane & 15);
        const int asw  = arow & 7;

        #pragma unroll
        for (int k0 = 0; k0 < 128; k0 += 16) {
            uint32_t a[4];
            int ch = ((k0 >> 3) + (lane >> 4)) ^ asw;
            ldmatrix_x4(a, hbase + arow * 256 + ch * 16);
            #pragma unroll
            for (int nt2 = 0; nt2 < 2; nt2++) {
                uint32_t bt[4];
                uint32_t baddr = w2b + (k0 + (lane & 15)) * 80
                               + ((lane >> 4) + 2 * nt2) * 16;
                ldmatrix_x4_trans(bt, baddr);
                mma_bf16(e[nt2 * 2 + 0], a, bt[0], bt[1]);
                mma_bf16(e[nt2 * 2 + 1], a, bt[2], bt[3]);
            }
        }

        float* Ep = g_Ep[ntile];
        #pragma unroll
        for (int j = 0; j < 4; j++) {
            int col = j * 8 + tg * 2;
            #pragma unroll
            for (int h2 = 0; h2 < 2; h2++) {
                int row = mtile * 128 + w * 16 + g + 8 * h2;
                if (col < TT)     Ep[(size_t)row * TT + col]     = e[j][2 * h2];
                if (col + 1 < TT) Ep[(size_t)row * TT + col + 1] = e[j][2 * h2 + 1];
            }
        }
    }
}

// ============================================================================
// reduce: E = sum_k Ep[k] + b2
// ============================================================================
__global__ __launch_bounds__(256)
void reduce_E_kernel(const float* __restrict__ b2)
{
    int i = blockIdx.x * 256 + threadIdx.x;
    if (i < MROWS * TT) {
        float s = g_Ep[0][i] + g_Ep[1][i] + g_Ep[2][i] + g_Ep[3][i];
        g_E[i] = s + __ldg(&b2[i % TT]);
    }
}

// ============================================================================
// CRF: one warp per batch element. Linear-domain scaled forward scan:
// per step: ONE warp-wide exp, 25 SHFL+FFMA matvec with Wexp=exp(trans), ONE log.
// Handles mask delivered as float32 / int32 / packed bytes, labels int64/int32.
// ============================================================================
__global__ void crf_kernel(const float* __restrict__ start_t,
                           const float* __restrict__ end_t,
                           const float* __restrict__ trans,
                           const void*  __restrict__ labels_raw,
                           const void*  __restrict__ mask_raw)
{
    __shared__ float trans_sh[TT * TT];
    __shared__ unsigned char msh[SS];

    const int b = blockIdx.x;
    const int lane = threadIdx.x;
    const unsigned full = 0xffffffffu;

    for (int i = lane; i < TT * TT; i += 32) trans_sh[i] = trans[i];

    // ---- detect label dtype: int64 vs int32 ----
    const int* li = (const int*)labels_raw;
    unsigned ball = __ballot_sync(full, li[2 * lane + 1] == 0);
    const int lstride = (ball == full) ? 2 : 1;

    // ---- detect mask encoding ----
    const unsigned* mw = (const unsigned*)mask_raw;
    unsigned any_high = 0, any_float = 0;
    for (int i = lane; i < 256; i += 32) {
        unsigned wv = mw[i];
        any_float |= (wv == 0x3F800000u);
        any_high  |= (wv & 0xFFFFFF00u) && (wv != 0x3F800000u);
    }
    const bool is_float = __ballot_sync(full, any_float != 0) != 0;
    const bool is_byte  = !is_float && (__ballot_sync(full, any_high != 0) != 0);

    const int base = b * SS;

    for (int t = lane; t < SS; t += 32) {
        unsigned char mv;
        if (is_float)      mv = (((const float*)mask_raw)[base + t] != 0.f);
        else if (is_byte)  mv = (((const unsigned char*)mask_raw)[base + t] != 0);
        else               mv = (((const int*)mask_raw)[base + t] != 0);
        msh[t] = mv;
    }
    __syncwarp();

    const float* Eb = g_E + (size_t)base * TT;

    // ---- numerator ----
    float acc = 0.f;
    int cnt = 0;
    for (int t = lane; t < SS; t += 32) cnt += msh[t] ? 1 : 0;
    for (int t = 1 + lane; t < SS; t += 32) {
        if (msh[t]) {
            int lt = li[(base + t) * lstride];
            int lp = li[(base + t - 1) * lstride];
            acc += trans_sh[lp * TT + lt] + Eb[t * TT + lt];
        }
    }
    #pragma unroll
    for (int off = 16; off > 0; off >>= 1) {
        acc += __shfl_xor_sync(full, acc, off);
        cnt += __shfl_xor_sync(full, cnt, off);
    }

    // ---- precompute Wexp column for this lane: wcol[i] = exp(trans[i][lane]) ----
    const int colSafe = (lane < TT) ? lane : (TT - 1);
    float wcol[TT];
    #pragma unroll
    for (int i = 0; i < TT; i++)
        wcol[i] = __expf(trans_sh[i * TT + colSafe]);

    // ---- forward scan (scaled linear domain) ----
    float alpha = (lane < TT) ? (start_t[lane] + Eb[lane]) : -INFINITY;

    float e_next = (lane < TT) ? Eb[1 * TT + lane] : 0.f;
    unsigned char m_next = msh[1];

    for (int t = 1; t < SS; t++) {
        float e_cur = e_next;
        unsigned char m_cur = m_next;
        if (t + 1 < SS) {
            e_next = (lane < TT) ? Eb[(t + 1) * TT + lane] : 0.f;
            m_next = msh[t + 1];
        }
        float M = __shfl_sync(full, alpha, 0);
        float p = __expf(alpha - M);   // lanes >= TT: exp(-inf)=0
        float a0 = 0.f, a1 = 0.f, a2 = 0.f, a3 = 0.f;
        #pragma unroll
        for (int i = 0; i < TT; i += 4) {
            a0 += __shfl_sync(full, p, i) * wcol[i];
            if (i + 1 < TT) a1 += __shfl_sync(full, p, i + 1) * wcol[i + 1];
            if (i + 2 < TT) a2 += __shfl_sync(full, p, i + 2) * wcol[i + 2];
            if (i + 3 < TT) a3 += __shfl_sync(full, p, i + 3) * wcol[i + 3];
        }
        float s = (a0 + a1) + (a2 + a3);
        float nv = e_cur + M + __logf(s);
        if (lane < TT && m_cur) alpha = nv;
    }

    float v = (lane < TT) ? (alpha + end_t[lane]) : -INFINITY;
    float M2 = v;
    #pragma unroll
    for (int off = 16; off > 0; off >>= 1)
        M2 = fmaxf(M2, __shfl_xor_sync(full, M2, off));
    float s2 = (lane < TT) ? __expf(v - M2) : 0.f;
    #pragma unroll
    for (int off = 16; off > 0; off >>= 1)
        s2 += __shfl_xor_sync(full, s2, off);

    if (lane == 0) {
        int lab0 = li[base * lstride];
        float score0 = start_t[lab0] + Eb[lab0];
        int last_idx = cnt - 1;
        int last_tag = li[(base + last_idx) * lstride];
        float numerator = score0 + acc + end_t[last_tag];
        float logZ = M2 + __logf(s2);
        g_ll[b] = numerator - logZ;
    }
}

// ============================================================================
// finalize: out = -mean(ll)
// ============================================================================
__global__ void finalize_kernel(float* __restrict__ out)
{
    __shared__ float sbuf[2];
    const int l = threadIdx.x; // 64 threads
    float v = g_ll[l];
    #pragma unroll
    for (int off = 16; off > 0; off >>= 1)
        v += __shfl_xor_sync(0xffffffffu, v, off);
    if ((l & 31) == 0) sbuf[l >> 5] = v;
    __syncthreads();
    if (l == 0) out[0] = -(sbuf[0] + sbuf[1]) / (float)BB;
}

// ============================================================================
// launch
// ============================================================================
extern "C" void kernel_launch(void* const* d_in, const int* in_sizes, int n_in,
                              void* d_out, int out_size)
{
    const float* X       = (const float*)d_in[0];
    const float* W1      = (const float*)d_in[1];
    const float* b1      = (const float*)d_in[2];
    const float* W2      = (const float*)d_in[3];
    const float* b2      = (const float*)d_in[4];
    const float* start_t = (const float*)d_in[5];
    const float* end_t   = (const float*)d_in[6];
    const float* trans   = (const float*)d_in[7];
    const void*  labels  = d_in[8];
    const void*  mask    = d_in[9];
    float* out = (float*)d_out;

    // bf16 conversion passes
    convert_X_kernel<<<(MROWS * DD / 8) / 256, 256>>>(X);
    convert_W1_kernel<<<(DD * HH / 8) / 256, 256>>>(W1);

    // GEMM1 (tensor cores) + gelu + fused GEMM2 partials
    dim3 g1(HH / 128, MROWS / 128);
    gemm1_fused_kernel<<<g1, 256>>>(b1, W2);

    // E = sum partials + b2
    reduce_E_kernel<<<(MROWS * TT + 255) / 256, 256>>>(b2);

    crf_kernel<<<BB, 32>>>(start_t, end_t, trans, labels, mask);

    finalize_kernel<<<1, 64>>>(out);
}